// round 14
// baseline (speedup 1.0000x reference)
#include <cuda_runtime.h>
#include <cuda_bf16.h>
#include <math.h>
#include <stdint.h>

#define NN 50000
#define NE 800000
#define NG 256
#define LN2F 0.69314718055994531f

// ---------------- scratch (device globals) ----------------
__device__ float g_h  [NN * 64];
__device__ float g_hs [NN * 128];   // h @ W1a + b1  (fp32)
__device__ float g_hd [NN * 128];   // h @ W1b       (fp32)
__device__ float g_agg[NN * 64];
__device__ float g_sums[NG];
__device__ float g_cnt [NG];
// split-planar bf16 edge activations, A-fragment slot layout:
//   per row: 16 hi u64 slots + 16 lo u64 slots (256B).
//   slot s = 4*kt + q holds bf16x2 pairs for cols (16kt+2q,+1) [.x] and (16kt+2q+8,+9) [.y]
__device__ uint2 g_ebf[(size_t)NE * 32];
// pre-packed B fragments: 3 layers x 192 frags x 32 lanes (uint4 = {bh01,bh23,bl01,bl23})
__device__ uint4 g_frags[3 * 6144];

typedef unsigned long long u64;

__device__ __forceinline__ u64 pack2(float lo, float hi) {
    u64 r; asm("mov.b64 %0, {%1, %2};" : "=l"(r) : "f"(lo), "f"(hi)); return r;
}
__device__ __forceinline__ void fma2(u64 &d, u64 a, u64 b) {
    asm("fma.rn.f32x2 %0, %1, %2, %0;" : "+l"(d) : "l"(a), "l"(b));
}
__device__ __forceinline__ float hsum2(u64 v) {
    float lo, hi; asm("mov.b64 {%0, %1}, %2;" : "=f"(lo), "=f"(hi) : "l"(v));
    return lo + hi;
}
__device__ __forceinline__ float ssp_f(float x) {
    return fmaxf(x, 0.0f) + __logf(1.0f + __expf(-fabsf(x))) - LN2F;
}
__device__ __forceinline__ void bfsplit2(float a, float b, uint32_t &hi, uint32_t &lo) {
    __nv_bfloat16 ha = __float2bfloat16_rn(a), hb = __float2bfloat16_rn(b);
    hi = (uint32_t)__bfloat16_as_ushort(ha) | ((uint32_t)__bfloat16_as_ushort(hb) << 16);
    __nv_bfloat16 la = __float2bfloat16_rn(a - __bfloat162float(ha));
    __nv_bfloat16 lb = __float2bfloat16_rn(b - __bfloat162float(hb));
    lo = (uint32_t)__bfloat16_as_ushort(la) | ((uint32_t)__bfloat16_as_ushort(lb) << 16);
}
__device__ __forceinline__ void pf_l2(const void* p) {
    asm volatile("prefetch.global.L2 [%0];" :: "l"(p));
}

__device__ __forceinline__ void mma_bf16(float* c,
    uint32_t a0, uint32_t a1, uint32_t a2, uint32_t a3, uint32_t b0, uint32_t b1) {
    asm("mma.sync.aligned.m16n8k16.row.col.f32.bf16.bf16.f32 "
        "{%0,%1,%2,%3}, {%4,%5,%6,%7}, {%8,%9}, {%0,%1,%2,%3};"
        : "+f"(c[0]), "+f"(c[1]), "+f"(c[2]), "+f"(c[3])
        : "r"(a0), "r"(a1), "r"(a2), "r"(a3), "r"(b0), "r"(b1));
}

// ---------------- fragment prep + pool zero (launch idx 0) ----------------
// Per layer, 192 fragments: [0,64)=W1c [64x128] (4kst x 16nt); [64,128)=W2 [128x64] (8x8);
// [128,160)=P1 [64x64] (4x8); [160,192)=P2 (4x8).
__global__ void k_prep_zero(const float* __restrict__ eu_w1, const float* __restrict__ eu_w2,
                            const float* __restrict__ pe1_w, const float* __restrict__ pe2_w) {
    int s = blockIdx.x * blockDim.x + threadIdx.x;
    if (s < NG) { g_sums[s] = 0.f; g_cnt[s] = 0.f; }
    if (s >= 3 * 6144) return;
    int l = s / 6144, r = s % 6144;
    int f = r >> 5, lane = r & 31;
    const float* W; int NT, N, fl;
    if (f < 64)       { W = eu_w1 + (size_t)l * 24576 + 16384; fl = f;       NT = 16; N = 128; } // W1c rows 128..191
    else if (f < 128) { W = eu_w2 + (size_t)l * 8192;          fl = f - 64;  NT = 8;  N = 64; }
    else if (f < 160) { W = pe1_w + (size_t)l * 4096;          fl = f - 128; NT = 8;  N = 64; }
    else              { W = pe2_w + (size_t)l * 4096;          fl = f - 160; NT = 8;  N = 64; }
    int nt = fl % NT, kst = fl / NT;
    int n  = nt * 8 + (lane >> 2);
    int k0 = kst * 16 + 2 * (lane & 3);
    float w0 = W[(size_t)k0 * N + n];
    float w1 = W[(size_t)(k0 + 1) * N + n];
    float w2 = W[(size_t)(k0 + 8) * N + n];
    float w3 = W[(size_t)(k0 + 9) * N + n];
    uint32_t h01, l01, h23, l23;
    bfsplit2(w0, w1, h01, l01);
    bfsplit2(w2, w3, h23, l23);
    g_frags[s] = make_uint4(h01, h23, l01, l23);
}

// ---------------- fused init: nodes (g_h + agg zero) and edges (g_ebf) (launch idx 1) ----------------
__global__ void k_init_all(const int* __restrict__ az, const float* __restrict__ emb,
                           const float* __restrict__ dist) {
    int t = blockIdx.x * blockDim.x + threadIdx.x;
    if (t < NN * 16) {
        int n = t >> 4, s = t & 15;
        int z = __ldg(az + n);
        float4 v = __ldg((const float4*)(emb + (size_t)z * 64) + s);
        ((float4*)(g_h + (size_t)n * 64))[s] = v;
        ((float4*)(g_agg + (size_t)n * 64))[s] = make_float4(0.f, 0.f, 0.f, 0.f);
        return;
    }
    int u = t - NN * 16;
    if (u >= NE * 16) return;
    int e = u >> 4, s = u & 15;
    int kt = s >> 2, q = s & 3;
    int k1 = 16 * kt + 2 * q;
    float d = __ldg(dist + e);
    const float gap = 63.0f / 5.0f, step = 5.0f / 63.0f;
    float v0, v1, v2, v3;
    { float df = d - step * (float)(k1);     v0 = __expf(-df * df * gap); }
    { float df = d - step * (float)(k1 + 1); v1 = __expf(-df * df * gap); }
    { float df = d - step * (float)(k1 + 8); v2 = __expf(-df * df * gap); }
    { float df = d - step * (float)(k1 + 9); v3 = __expf(-df * df * gap); }
    uint32_t h0, l0, h1, l1;
    bfsplit2(v0, v1, h0, l0);
    bfsplit2(v2, v3, h1, l1);
    g_ebf[(size_t)e * 32 + s]      = make_uint2(h0, h1);
    g_ebf[(size_t)e * 32 + 16 + s] = make_uint2(l0, l1);
}

// ---------------- node-pre device function (fp32, fma2) ----------------
__device__ __forceinline__ void pre_group(const float* __restrict__ sPreT,
                                          const float* __restrict__ scrN,
                                          const float* __restrict__ b1g,
                                          int n0, int lane) {
#pragma unroll
    for (int half = 0; half < 2; half++) {
        u64 p[4][4];
#pragma unroll
        for (int i = 0; i < 4; i++)
#pragma unroll
            for (int j = 0; j < 4; j++) p[i][j] = 0ULL;
        const float* w0 = sPreT + (half * 128 + lane     ) * 68;
        const float* w1 = sPreT + (half * 128 + lane + 32) * 68;
        const float* w2 = sPreT + (half * 128 + lane + 64) * 68;
        const float* w3 = sPreT + (half * 128 + lane + 96) * 68;
#pragma unroll 4
        for (int k = 0; k < 64; k += 4) {
            ulonglong2 a = *(const ulonglong2*)(w0 + k);
            ulonglong2 b = *(const ulonglong2*)(w1 + k);
            ulonglong2 c = *(const ulonglong2*)(w2 + k);
            ulonglong2 d = *(const ulonglong2*)(w3 + k);
#pragma unroll
            for (int i = 0; i < 4; i++) {
                ulonglong2 t = *(const ulonglong2*)(scrN + i * 64 + k);
                fma2(p[i][0], t.x, a.x); fma2(p[i][0], t.y, a.y);
                fma2(p[i][1], t.x, b.x); fma2(p[i][1], t.y, b.y);
                fma2(p[i][2], t.x, c.x); fma2(p[i][2], t.y, c.y);
                fma2(p[i][3], t.x, d.x); fma2(p[i][3], t.y, d.y);
            }
        }
        float bz0 = 0.f, bz1 = 0.f, bz2 = 0.f, bz3 = 0.f;
        if (half == 0) {
            bz0 = __ldg(b1g + lane);      bz1 = __ldg(b1g + lane + 32);
            bz2 = __ldg(b1g + lane + 64); bz3 = __ldg(b1g + lane + 96);
        }
        float* out = (half == 0) ? g_hs : g_hd;
#pragma unroll
        for (int i = 0; i < 4; i++) {
            float* o = out + (size_t)(n0 + i) * 128;
            o[lane]      = hsum2(p[i][0]) + bz0;
            o[lane + 32] = hsum2(p[i][1]) + bz1;
            o[lane + 64] = hsum2(p[i][2]) + bz2;
            o[lane + 96] = hsum2(p[i][3]) + bz3;
        }
    }
}

// ---------------- layer-0 node pre (launch idx 2) ----------------
__global__ void __launch_bounds__(512, 1) k_pre0(const float* __restrict__ w1, const float* __restrict__ b1g) {
    extern __shared__ float sm[];
    float* sPreT = sm;
    float* sScr  = sm + 17408;
    int tid = threadIdx.x;
    for (int i = tid; i < 16384; i += 512) {
        int k = i >> 7, c = i & 127;
        int row = (k < 64) ? c : (128 + c);
        sPreT[row * 68 + (k & 63)] = w1[i];
    }
    __syncthreads();
    int lane = tid & 31, warp = tid >> 5;
    float* scrN = sScr + warp * 256;
    const int stride = gridDim.x * 16;
    for (int g = blockIdx.x * 16 + warp; g < NN / 4; g += stride) {
        int n0 = g * 4;
        const float4* hsrc = (const float4*)(g_h + (size_t)n0 * 64);
        ((float4*)scrN)[lane]      = hsrc[lane];
        ((float4*)scrN)[lane + 32] = hsrc[lane + 32];
        __syncwarp();
        pre_group(sPreT, scrN, b1g, n0, lane);
        __syncwarp();
    }
}

// ---------------- smem layout for k_edge_mma ----------------
#define FRAG_U4   6144                  // 192 frags * 32 lanes
#define SM_BIAS2  (FRAG_U4 * 16)        // 98304 B : b2[64]
#define SM_Q1     (SM_BIAS2 + 256)
#define SM_Q2     (SM_Q1 + 256)
#define EDGE_SMEM (SM_Q2 + 256)         // 99072 B

#define FR1 0
#define FR2 (64 * 32)
#define FR3 (128 * 32)
#define FR4 (160 * 32)

// ---------------- mma.sync edge kernel: M=16/warp, 384 thr, L2-prefetched gathers ----------------
__global__ void __launch_bounds__(384, 1) k_edge_mma(
    int layer, int store_e,
    const int* __restrict__ src, const int* __restrict__ dst,
    const float* __restrict__ b2,
    const float* __restrict__ pb1, const float* __restrict__ pb2)
{
    extern __shared__ char smem[];
    uint4* sm4 = (uint4*)smem;
    const int tid = threadIdx.x;

    {
        const uint4* srcf = g_frags + (size_t)layer * FRAG_U4;
        for (int i = tid; i < FRAG_U4; i += 384) sm4[i] = srcf[i];
        float* sB2 = (float*)(smem + SM_BIAS2);
        float* sQ1 = (float*)(smem + SM_Q1);
        float* sQ2 = (float*)(smem + SM_Q2);
        if (tid < 64) { sB2[tid] = b2[tid]; sQ1[tid] = pb1[tid]; sQ2[tid] = pb2[tid]; }
    }
    __syncthreads();

    const float* sB2f = (const float*)(smem + SM_BIAS2);
    const float* sQ1f = (const float*)(smem + SM_Q1);
    const float* sQ2f = (const float*)(smem + SM_Q2);

    const int wid = tid >> 5, lane = tid & 31;
    const int gr = lane >> 2;
    const int q  = lane & 3;
    const int t2 = 2 * q;

    const int NTILES = NE / 16;          // 50000
    const int wstride = gridDim.x * 12;

    int tile = blockIdx.x * 12 + wid;
    int pis0 = 0, pis8 = 0, pid0 = 0, pid8 = 0;
    if (tile < NTILES) {
        pis0 = __ldg(src + tile * 16 + gr);  pis8 = __ldg(src + tile * 16 + gr + 8);
        pid0 = __ldg(dst + tile * 16 + gr);  pid8 = __ldg(dst + tile * 16 + gr + 8);
        // warm L2 for the first tile's gathers (each lane covers its 128B line, q in 0..3)
        pf_l2(g_hs + (size_t)pis0 * 128 + q * 32);
        pf_l2(g_hd + (size_t)pid0 * 128 + q * 32);
        pf_l2(g_hs + (size_t)pis8 * 128 + q * 32);
        pf_l2(g_hd + (size_t)pid8 * 128 + q * 32);
    }

    for (; tile < NTILES; tile += wstride) {
        const int base = tile * 16;
        const int r0 = base + gr, r1 = base + gr + 8;
        const int is0 = pis0, is8 = pis8, id0 = pid0, id8 = pid8;
        {
            int tn = tile + wstride;
            if (tn < NTILES) {
                pis0 = __ldg(src + tn * 16 + gr); pis8 = __ldg(src + tn * 16 + gr + 8);
                pid0 = __ldg(dst + tn * 16 + gr); pid8 = __ldg(dst + tn * 16 + gr + 8);
                // L2 prefetch next tile's hs/hd rows (512B each; lane covers line q)
                pf_l2(g_hs + (size_t)pis0 * 128 + q * 32);
                pf_l2(g_hd + (size_t)pid0 * 128 + q * 32);
                pf_l2(g_hs + (size_t)pis8 * 128 + q * 32);
                pf_l2(g_hd + (size_t)pid8 * 128 + q * 32);
                // L2 prefetch next tile's e rows (256B each = 2 lines; lanes q=0,1 row0 / q=2,3 row1)
                const char* er = (const char*)(g_ebf + (size_t)(tn * 16 + gr + (q >> 1) * 8) * 32);
                pf_l2(er + (q & 1) * 128);
            }
        }

        // ============ stage 1: c1 init = hs[src] + hd[dst]; then c1 += e @ W1c ============
        float c1[16][4];
        {
            const float* hs0 = g_hs + (size_t)is0 * 128;
            const float* hd0 = g_hd + (size_t)id0 * 128;
            const float* hs8 = g_hs + (size_t)is8 * 128;
            const float* hd8 = g_hd + (size_t)id8 * 128;
#pragma unroll
            for (int nt = 0; nt < 16; nt++) {
                float2 a = __ldg((const float2*)(hs0 + nt * 8 + t2));
                float2 b = __ldg((const float2*)(hd0 + nt * 8 + t2));
                float2 c = __ldg((const float2*)(hs8 + nt * 8 + t2));
                float2 d = __ldg((const float2*)(hd8 + nt * 8 + t2));
                c1[nt][0] = a.x + b.x; c1[nt][1] = a.y + b.y;
                c1[nt][2] = c.x + d.x; c1[nt][3] = c.y + d.y;
            }
        }
        {
            const uint2* pe0 = g_ebf + (size_t)r0 * 32;
            const uint2* pe1 = g_ebf + (size_t)r1 * 32;
            uint2 h0b[2], h1b[2], l0b[2], l1b[2];
            h0b[0] = __ldg(pe0 + q);      h1b[0] = __ldg(pe1 + q);
            l0b[0] = __ldg(pe0 + 16 + q); l1b[0] = __ldg(pe1 + 16 + q);
#pragma unroll
            for (int kt = 0; kt < 4; kt++) {
                const int cb = kt & 1, nb = cb ^ 1;
                if (kt < 3) {
                    h0b[nb] = __ldg(pe0 + 4 * (kt + 1) + q);      h1b[nb] = __ldg(pe1 + 4 * (kt + 1) + q);
                    l0b[nb] = __ldg(pe0 + 16 + 4 * (kt + 1) + q); l1b[nb] = __ldg(pe1 + 16 + 4 * (kt + 1) + q);
                }
                const uint4* fp = sm4 + FR1 + (size_t)kt * 512 + lane;
#pragma unroll
                for (int nt = 0; nt < 16; nt++) {
                    uint4 f = fp[nt * 32];
                    mma_bf16(c1[nt], h0b[cb].x, h1b[cb].x, h0b[cb].y, h1b[cb].y, f.x, f.y);
                    mma_bf16(c1[nt], l0b[cb].x, l1b[cb].x, l0b[cb].y, l1b[cb].y, f.x, f.y);
                    mma_bf16(c1[nt], h0b[cb].x, h1b[cb].x, h0b[cb].y, h1b[cb].y, f.z, f.w);
                }
            }
        }

        // ============ epi1+stage2 interleaved per kt: C2 = ssp(C1) @ W2 (b1 folded into hs) ============
        float c2[8][4];
#pragma unroll
        for (int nt = 0; nt < 8; nt++) { c2[nt][0] = c2[nt][1] = c2[nt][2] = c2[nt][3] = 0.f; }
#pragma unroll 1
        for (int kt = 0; kt < 8; kt++) {
            uint32_t a2h[4], a2l[4];
#pragma unroll
            for (int half = 0; half < 2; half++) {
                int nt = 2 * kt + half;
                float v0 = ssp_f(c1[nt][0]), v1 = ssp_f(c1[nt][1]);
                float v2 = ssp_f(c1[nt][2]), v3 = ssp_f(c1[nt][3]);
                bfsplit2(v0, v1, a2h[2 * half],     a2l[2 * half]);
                bfsplit2(v2, v3, a2h[2 * half + 1], a2l[2 * half + 1]);
            }
            const uint4* fp = sm4 + FR2 + (size_t)kt * 8 * 32 + lane;
#pragma unroll
            for (int nt = 0; nt < 8; nt++) {
                uint4 f = fp[nt * 32];
                mma_bf16(c2[nt], a2h[0], a2h[1], a2h[2], a2h[3], f.x, f.y);
                mma_bf16(c2[nt], a2l[0], a2l[1], a2l[2], a2l[3], f.x, f.y);
                mma_bf16(c2[nt], a2h[0], a2h[1], a2h[2], a2h[3], f.z, f.w);
            }
        }

        // ============ epi2+stage3 interleaved: C3 = (C2+b2) @ P1 ; e' -> g_ebf ============
        float c3[8][4];
#pragma unroll
        for (int nt = 0; nt < 8; nt++) { c3[nt][0] = c3[nt][1] = c3[nt][2] = c3[nt][3] = 0.f; }
#pragma unroll 1
        for (int kt = 0; kt < 4; kt++) {
            uint32_t a3h[4], a3l[4];
#pragma unroll
            for (int half = 0; half < 2; half++) {
                int nt = 2 * kt + half;
                float2 bb = *(const float2*)(sB2f + nt * 8 + t2);
                float x0 = c2[nt][0] + bb.x, x1 = c2[nt][1] + bb.y;
                float x2 = c2[nt][2] + bb.x, x3 = c2[nt][3] + bb.y;
                bfsplit2(x0, x1, a3h[2 * half],     a3l[2 * half]);
                bfsplit2(x2, x3, a3h[2 * half + 1], a3l[2 * half + 1]);
            }
            if (store_e) {
                uint2* pe0 = g_ebf + (size_t)r0 * 32;
                uint2* pe1 = g_ebf + (size_t)r1 * 32;
                pe0[4 * kt + q]      = make_uint2(a3h[0], a3h[2]);
                pe1[4 * kt + q]      = make_uint2(a3h[1], a3h[3]);
                pe0[16 + 4 * kt + q] = make_uint2(a3l[0], a3l[2]);
                pe1[16 + 4 * kt + q] = make_uint2(a3l[1], a3l[3]);
            }
            const uint4* fp = sm4 + FR3 + (size_t)kt * 8 * 32 + lane;
#pragma unroll
            for (int nt = 0; nt < 8; nt++) {
                uint4 f = fp[nt * 32];
                mma_bf16(c3[nt], a3h[0], a3h[1], a3h[2], a3h[3], f.x, f.y);
                mma_bf16(c3[nt], a3l[0], a3l[1], a3l[2], a3l[3], f.x, f.y);
                mma_bf16(c3[nt], a3h[0], a3h[1], a3h[2], a3h[3], f.z, f.w);
            }
        }

        // ============ epi3+stage4 interleaved: C4 = ssp(C3+q1) @ P2 ============
        float c4[8][4];
#pragma unroll
        for (int nt = 0; nt < 8; nt++) { c4[nt][0] = c4[nt][1] = c4[nt][2] = c4[nt][3] = 0.f; }
#pragma unroll 1
        for (int kt = 0; kt < 4; kt++) {
            uint32_t a4h[4], a4l[4];
#pragma unroll
            for (int half = 0; half < 2; half++) {
                int nt = 2 * kt + half;
                float2 bb = *(const float2*)(sQ1f + nt * 8 + t2);
                float v0 = ssp_f(c3[nt][0] + bb.x), v1 = ssp_f(c3[nt][1] + bb.y);
                float v2 = ssp_f(c3[nt][2] + bb.x), v3 = ssp_f(c3[nt][3] + bb.y);
                bfsplit2(v0, v1, a4h[2 * half],     a4l[2 * half]);
                bfsplit2(v2, v3, a4h[2 * half + 1], a4l[2 * half + 1]);
            }
            const uint4* fp = sm4 + FR4 + (size_t)kt * 8 * 32 + lane;
#pragma unroll
            for (int nt = 0; nt < 8; nt++) {
                uint4 f = fp[nt * 32];
                mma_bf16(c4[nt], a4h[0], a4h[1], a4h[2], a4h[3], f.x, f.y);
                mma_bf16(c4[nt], a4l[0], a4l[1], a4l[2], a4l[3], f.x, f.y);
                mma_bf16(c4[nt], a4h[0], a4h[1], a4h[2], a4h[3], f.z, f.w);
            }
        }

        // ============ epi4: he = C4 + q2; scatter-add to g_agg[dst] ============
        {
            float* da = g_agg + (size_t)id0 * 64;
            float* db = g_agg + (size_t)id8 * 64;
#pragma unroll
            for (int nt = 0; nt < 8; nt++) {
                float2 bb = *(const float2*)(sQ2f + nt * 8 + t2);
                float x0 = c4[nt][0] + bb.x, x1 = c4[nt][1] + bb.y;
                float x2 = c4[nt][2] + bb.x, x3 = c4[nt][3] + bb.y;
                asm volatile("red.global.add.v2.f32 [%0], {%1, %2};"
                             :: "l"(da + nt * 8 + t2), "f"(x0), "f"(x1) : "memory");
                asm volatile("red.global.add.v2.f32 [%0], {%1, %2};"
                             :: "l"(db + nt * 8 + t2), "f"(x2), "f"(x3) : "memory");
            }
        }
    }
}

// ---------------- node update: h += ssp(agg@A+ba)@B + bb; agg=0; fused next-layer pre ----------------
#define UPD_SMEM_FLOATS 30336
__global__ void __launch_bounds__(512, 1) k_update(
    const float* __restrict__ wa, const float* __restrict__ ba,
    const float* __restrict__ wb, const float* __restrict__ bb_,
    const float* __restrict__ w1next, const float* __restrict__ b1next, int do_pre)
{
    extern __shared__ float sm[];
    float* sPreT = sm;
    float* sAT   = sm + 17408;
    float* sBT   = sm + 21760;
    float* sBa   = sm + 26112;
    float* sBb   = sm + 26176;
    float* sScr  = sm + 26240;
    int tid = threadIdx.x;
    for (int i = tid; i < 4096; i += 512) {
        int k = i >> 6, c = i & 63;
        sAT[c * 68 + k] = wa[i];
        sBT[c * 68 + k] = wb[i];
    }
    if (do_pre) {
        for (int i = tid; i < 16384; i += 512) {
            int k = i >> 7, c = i & 127;
            int row = (k < 64) ? c : (128 + c);
            sPreT[row * 68 + (k & 63)] = w1next[i];
        }
    }
    if (tid < 64) { sBa[tid] = ba[tid]; sBb[tid] = bb_[tid]; }
    __syncthreads();

    int lane = tid & 31, warp = tid >> 5;
    float* scrN = sScr + warp * 256;
    const float bav0 = sBa[lane], bav1 = sBa[lane + 32];
    const float bbv0 = sBb[lane], bbv1 = sBb[lane + 32];
    const float* a0p = sAT + lane * 68;
    const float* a1p = sAT + (lane + 32) * 68;
    const float* b0p = sBT + lane * 68;
    const float* b1p = sBT + (lane + 32) * 68;
    const int stride = gridDim.x * 16;

    for (int g = blockIdx.x * 16 + warp; g < NN / 4; g += stride) {
        int n0 = g * 4;
        float4* av = (float4*)(g_agg + (size_t)n0 * 64);
        float4 z = make_float4(0.f, 0.f, 0.f, 0.f);
        float4 t0 = av[lane], t1v = av[lane + 32];
        ((float4*)scrN)[lane] = t0; ((float4*)scrN)[lane + 32] = t1v;
        av[lane] = z; av[lane + 32] = z;
        __syncwarp();
        u64 aa[4][2];
#pragma unroll
        for (int i = 0; i < 4; i++) { aa[i][0] = pack2(bav0, 0.f); aa[i][1] = pack2(bav1, 0.f); }
#pragma unroll 4
        for (int k = 0; k < 64; k += 4) {
            ulonglong2 w0 = *(const ulonglong2*)(a0p + k);
            ulonglong2 w1 = *(const ulonglong2*)(a1p + k);
#pragma unroll
            for (int i = 0; i < 4; i++) {
                ulonglong2 tt = *(const ulonglong2*)(scrN + i * 64 + k);
                fma2(aa[i][0], tt.x, w0.x); fma2(aa[i][0], tt.y, w0.y);
                fma2(aa[i][1], tt.x, w1.x); fma2(aa[i][1], tt.y, w1.y);
            }
        }
        __syncwarp();
#pragma unroll
        for (int i = 0; i < 4; i++) {
            scrN[i * 64 + lane]      = ssp_f(hsum2(aa[i][0]));
            scrN[i * 64 + lane + 32] = ssp_f(hsum2(aa[i][1]));
        }
        __syncwarp();
        u64 oo[4][2];
#pragma unroll
        for (int i = 0; i < 4; i++) { oo[i][0] = pack2(bbv0, 0.f); oo[i][1] = pack2(bbv1, 0.f); }
#pragma unroll 4
        for (int k = 0; k < 64; k += 4) {
            ulonglong2 w0 = *(const ulonglong2*)(b0p + k);
            ulonglong2 w1 = *(const ulonglong2*)(b1p + k);
#pragma unroll
            for (int i = 0; i < 4; i++) {
                ulonglong2 tt = *(const ulonglong2*)(scrN + i * 64 + k);
                fma2(oo[i][0], tt.x, w0.x); fma2(oo[i][0], tt.y, w0.y);
                fma2(oo[i][1], tt.x, w1.x); fma2(oo[i][1], tt.y, w1.y);
            }
        }
        __syncwarp();
#pragma unroll
        for (int i = 0; i < 4; i++) {
            float* hp = g_h + (size_t)(n0 + i) * 64;
            float h0 = hp[lane]      + hsum2(oo[i][0]);
            float h1 = hp[lane + 32] + hsum2(oo[i][1]);
            hp[lane] = h0; hp[lane + 32] = h1;
            scrN[i * 64 + lane] = h0; scrN[i * 64 + lane + 32] = h1;
        }
        __syncwarp();
        if (do_pre) { pre_group(sPreT, scrN, b1next, n0, lane); }
        __syncwarp();
    }
}

// ---------------- readout + per-graph mean ----------------
__global__ void __launch_bounds__(256) k_readout(
    const int* __restrict__ gid,
    const float* __restrict__ d1w, const float* __restrict__ d1b,
    const float* __restrict__ d2w, const float* __restrict__ d2b)
{
    __shared__ float sW[2048], sB1r[32], sW2r[32];
    __shared__ float sB2r;
    int tid = threadIdx.x;
    for (int i = tid; i < 2048; i += 256) sW[i] = d1w[i];
    if (tid < 32) { sB1r[tid] = d1b[tid]; sW2r[tid] = d2w[tid]; }
    if (tid == 0) sB2r = d2b[0];
    __syncthreads();
    int lane = tid & 31, warp = tid >> 5;
    int nw = gridDim.x * 8;
    for (int n = blockIdx.x * 8 + warp; n < NN; n += nw) {
        float2 hv = *(const float2*)(g_h + (size_t)n * 64 + 2 * lane);
        float a = sB1r[lane];
#pragma unroll 8
        for (int k = 0; k < 64; k++) {
            float ek = __shfl_sync(0xffffffffu, (k & 1) ? hv.y : hv.x, k >> 1);
            a = fmaf(ek, sW[k * 32 + lane], a);
        }
        float p = ssp_f(a) * sW2r[lane];
#pragma unroll
        for (int off = 16; off; off >>= 1) p += __shfl_xor_sync(0xffffffffu, p, off);
        if (lane == 0) {
            int g = gid[n];
            atomicAdd(&g_sums[g], p + sB2r);
            atomicAdd(&g_cnt[g], 1.0f);
        }
    }
}

__global__ void k_final(float* __restrict__ out) {
    int t = threadIdx.x;
    if (t < NG) out[t] = g_sums[t] / fmaxf(g_cnt[t], 1.0f);
}

// ---------------- launch ----------------
extern "C" void kernel_launch(void* const* d_in, const int* in_sizes, int n_in,
                              void* d_out, int out_size) {
    const int*   az     = (const int*)d_in[0];
    const float* dist   = (const float*)d_in[1];
    const int*   src    = (const int*)d_in[2];
    const int*   dst    = (const int*)d_in[3];
    const int*   gid    = (const int*)d_in[4];
    const float* emb    = (const float*)d_in[5];
    const float* eu_w1  = (const float*)d_in[6];
    const float* eu_b1  = (const float*)d_in[7];
    const float* eu_w2  = (const float*)d_in[8];
    const float* eu_b2  = (const float*)d_in[9];
    const float* pe1_w  = (const float*)d_in[10];
    const float* pe1_b  = (const float*)d_in[11];
    const float* pe2_w  = (const float*)d_in[12];
    const float* pe2_b  = (const float*)d_in[13];
    const float* pn2a_w = (const float*)d_in[14];
    const float* pn2a_b = (const float*)d_in[15];
    const float* pn2b_w = (const float*)d_in[16];
    const float* pn2b_b = (const float*)d_in[17];
    const float* d1w    = (const float*)d_in[18];
    const float* d1b    = (const float*)d_in[19];
    const float* d2w    = (const float*)d_in[20];
    const float* d2b    = (const float*)d_in[21];

    cudaFuncSetAttribute(k_edge_mma, cudaFuncAttributeMaxDynamicSharedMemorySize, EDGE_SMEM);
    cudaFuncSetAttribute(k_update,   cudaFuncAttributeMaxDynamicSharedMemorySize, UPD_SMEM_FLOATS * 4);
    cudaFuncSetAttribute(k_pre0,     cudaFuncAttributeMaxDynamicSharedMemorySize, 21504 * 4);

    k_prep_zero<<<(3 * 6144 + 255) / 256, 256>>>(eu_w1, eu_w2, pe1_w, pe2_w);      // idx 0
    k_init_all<<<((NN + NE) * 16 + 255) / 256, 256>>>(az, emb, dist);              // idx 1
    k_pre0<<<148, 512, 21504 * 4>>>(eu_w1, eu_b1);                                 // idx 2

    for (int l = 0; l < 3; l++) {
        k_edge_mma<<<148, 384, EDGE_SMEM>>>(                                        // idx 3 (l=0)
            l, (l < 2) ? 1 : 0, src, dst,
            eu_b2 + l * 64, pe1_b + l * 64, pe2_b + l * 64);
        k_update<<<148, 512, UPD_SMEM_FLOATS * 4>>>(
            pn2a_w + (size_t)l * 4096, pn2a_b + l * 64,
            pn2b_w + (size_t)l * 4096, pn2b_b + l * 64,
            eu_w1 + (size_t)(l + 1) * 24576, eu_b1 + (size_t)(l + 1) * 128,
            (l < 2) ? 1 : 0);
    }
    k_readout<<<296, 256>>>(gid, d1w, d1b, d2w, d2b);
    k_final<<<1, 256>>>((float*)d_out);
}

// round 15
// speedup vs baseline: 1.1254x; 1.1254x over previous
#include <cuda_runtime.h>
#include <cuda_bf16.h>
#include <math.h>
#include <stdint.h>

#define NN 50000
#define NE 800000
#define NG 256
#define LN2F 0.69314718055994531f

// ---------------- scratch (device globals) ----------------
__device__ float g_h  [NN * 64];
// hs/hd rows stored PERMUTED: position p = 16*(nt>>1) + 4*(cc>>1) + 2*(nt&1) + (cc&1)
// for logical col c = 8*nt + cc. Lane q's A-fragment share is contiguous float4s at 16j+4q.
__device__ float g_hs [NN * 128];   // perm(h @ W1a + b1)  (fp32)
__device__ float g_hd [NN * 128];   // perm(h @ W1b)       (fp32)
__device__ float g_agg[NN * 64];
__device__ float g_sums[NG];
__device__ float g_cnt [NG];
// split-planar bf16 edge activations (A-fragment slot layout; 16 hi + 16 lo u64 slots/row)
__device__ uint2 g_ebf[(size_t)NE * 32];
// pre-packed B fragments: 3 layers x 192 frags x 32 lanes (uint4 = {bh01,bh23,bl01,bl23})
__device__ uint4 g_frags[3 * 6144];

typedef unsigned long long u64;

__device__ __forceinline__ u64 pack2(float lo, float hi) {
    u64 r; asm("mov.b64 %0, {%1, %2};" : "=l"(r) : "f"(lo), "f"(hi)); return r;
}
__device__ __forceinline__ void fma2(u64 &d, u64 a, u64 b) {
    asm("fma.rn.f32x2 %0, %1, %2, %0;" : "+l"(d) : "l"(a), "l"(b));
}
__device__ __forceinline__ float hsum2(u64 v) {
    float lo, hi; asm("mov.b64 {%0, %1}, %2;" : "=f"(lo), "=f"(hi) : "l"(v));
    return lo + hi;
}
__device__ __forceinline__ float ssp_f(float x) {
    return fmaxf(x, 0.0f) + __logf(1.0f + __expf(-fabsf(x))) - LN2F;
}
__device__ __forceinline__ void bfsplit2(float a, float b, uint32_t &hi, uint32_t &lo) {
    __nv_bfloat16 ha = __float2bfloat16_rn(a), hb = __float2bfloat16_rn(b);
    hi = (uint32_t)__bfloat16_as_ushort(ha) | ((uint32_t)__bfloat16_as_ushort(hb) << 16);
    __nv_bfloat16 la = __float2bfloat16_rn(a - __bfloat162float(ha));
    __nv_bfloat16 lb = __float2bfloat16_rn(b - __bfloat162float(hb));
    lo = (uint32_t)__bfloat16_as_ushort(la) | ((uint32_t)__bfloat16_as_ushort(lb) << 16);
}
// permuted position for logical column c (0..127)
__device__ __forceinline__ int permp(int c) {
    int nt = c >> 3, cc = c & 7;
    return 16 * (nt >> 1) + 4 * (cc >> 1) + 2 * (nt & 1) + (cc & 1);
}

__device__ __forceinline__ void mma_bf16(float* c,
    uint32_t a0, uint32_t a1, uint32_t a2, uint32_t a3, uint32_t b0, uint32_t b1) {
    asm("mma.sync.aligned.m16n8k16.row.col.f32.bf16.bf16.f32 "
        "{%0,%1,%2,%3}, {%4,%5,%6,%7}, {%8,%9}, {%0,%1,%2,%3};"
        : "+f"(c[0]), "+f"(c[1]), "+f"(c[2]), "+f"(c[3])
        : "r"(a0), "r"(a1), "r"(a2), "r"(a3), "r"(b0), "r"(b1));
}

// ---------------- fragment prep + pool zero (launch idx 0) ----------------
__global__ void k_prep_zero(const float* __restrict__ eu_w1, const float* __restrict__ eu_w2,
                            const float* __restrict__ pe1_w, const float* __restrict__ pe2_w) {
    int s = blockIdx.x * blockDim.x + threadIdx.x;
    if (s < NG) { g_sums[s] = 0.f; g_cnt[s] = 0.f; }
    if (s >= 3 * 6144) return;
    int l = s / 6144, r = s % 6144;
    int f = r >> 5, lane = r & 31;
    const float* W; int NT, N, fl;
    if (f < 64)       { W = eu_w1 + (size_t)l * 24576 + 16384; fl = f;       NT = 16; N = 128; }
    else if (f < 128) { W = eu_w2 + (size_t)l * 8192;          fl = f - 64;  NT = 8;  N = 64; }
    else if (f < 160) { W = pe1_w + (size_t)l * 4096;          fl = f - 128; NT = 8;  N = 64; }
    else              { W = pe2_w + (size_t)l * 4096;          fl = f - 160; NT = 8;  N = 64; }
    int nt = fl % NT, kst = fl / NT;
    int n  = nt * 8 + (lane >> 2);
    int k0 = kst * 16 + 2 * (lane & 3);
    float w0 = W[(size_t)k0 * N + n];
    float w1 = W[(size_t)(k0 + 1) * N + n];
    float w2 = W[(size_t)(k0 + 8) * N + n];
    float w3 = W[(size_t)(k0 + 9) * N + n];
    uint32_t h01, l01, h23, l23;
    bfsplit2(w0, w1, h01, l01);
    bfsplit2(w2, w3, h23, l23);
    g_frags[s] = make_uint4(h01, h23, l01, l23);
}

// ---------------- fused init: nodes (g_h + agg zero) and edges (g_ebf) (launch idx 1) ----------------
__global__ void k_init_all(const int* __restrict__ az, const float* __restrict__ emb,
                           const float* __restrict__ dist) {
    int t = blockIdx.x * blockDim.x + threadIdx.x;
    if (t < NN * 16) {
        int n = t >> 4, s = t & 15;
        int z = __ldg(az + n);
        float4 v = __ldg((const float4*)(emb + (size_t)z * 64) + s);
        ((float4*)(g_h + (size_t)n * 64))[s] = v;
        ((float4*)(g_agg + (size_t)n * 64))[s] = make_float4(0.f, 0.f, 0.f, 0.f);
        return;
    }
    int u = t - NN * 16;
    if (u >= NE * 16) return;
    int e = u >> 4, s = u & 15;
    int kt = s >> 2, q = s & 3;
    int k1 = 16 * kt + 2 * q;
    float d = __ldg(dist + e);
    const float gap = 63.0f / 5.0f, step = 5.0f / 63.0f;
    float v0, v1, v2, v3;
    { float df = d - step * (float)(k1);     v0 = __expf(-df * df * gap); }
    { float df = d - step * (float)(k1 + 1); v1 = __expf(-df * df * gap); }
    { float df = d - step * (float)(k1 + 8); v2 = __expf(-df * df * gap); }
    { float df = d - step * (float)(k1 + 9); v3 = __expf(-df * df * gap); }
    uint32_t h0, l0, h1, l1;
    bfsplit2(v0, v1, h0, l0);
    bfsplit2(v2, v3, h1, l1);
    g_ebf[(size_t)e * 32 + s]      = make_uint2(h0, h1);
    g_ebf[(size_t)e * 32 + 16 + s] = make_uint2(l0, l1);
}

// ---------------- node-pre device function (fp32, fma2) ----------------
// writes PERMUTED g_hs (+ b1) and g_hd
__device__ __forceinline__ void pre_group(const float* __restrict__ sPreT,
                                          const float* __restrict__ scrN,
                                          const float* __restrict__ b1g,
                                          int n0, int lane,
                                          int p0, int p1, int p2, int p3) {
#pragma unroll
    for (int half = 0; half < 2; half++) {
        u64 p[4][4];
#pragma unroll
        for (int i = 0; i < 4; i++)
#pragma unroll
            for (int j = 0; j < 4; j++) p[i][j] = 0ULL;
        const float* w0 = sPreT + (half * 128 + lane     ) * 68;
        const float* w1 = sPreT + (half * 128 + lane + 32) * 68;
        const float* w2 = sPreT + (half * 128 + lane + 64) * 68;
        const float* w3 = sPreT + (half * 128 + lane + 96) * 68;
#pragma unroll 4
        for (int k = 0; k < 64; k += 4) {
            ulonglong2 a = *(const ulonglong2*)(w0 + k);
            ulonglong2 b = *(const ulonglong2*)(w1 + k);
            ulonglong2 c = *(const ulonglong2*)(w2 + k);
            ulonglong2 d = *(const ulonglong2*)(w3 + k);
#pragma unroll
            for (int i = 0; i < 4; i++) {
                ulonglong2 t = *(const ulonglong2*)(scrN + i * 64 + k);
                fma2(p[i][0], t.x, a.x); fma2(p[i][0], t.y, a.y);
                fma2(p[i][1], t.x, b.x); fma2(p[i][1], t.y, b.y);
                fma2(p[i][2], t.x, c.x); fma2(p[i][2], t.y, c.y);
                fma2(p[i][3], t.x, d.x); fma2(p[i][3], t.y, d.y);
            }
        }
        float bz0 = 0.f, bz1 = 0.f, bz2 = 0.f, bz3 = 0.f;
        if (half == 0) {
            bz0 = __ldg(b1g + lane);      bz1 = __ldg(b1g + lane + 32);
            bz2 = __ldg(b1g + lane + 64); bz3 = __ldg(b1g + lane + 96);
        }
        float* out = (half == 0) ? g_hs : g_hd;
#pragma unroll
        for (int i = 0; i < 4; i++) {
            float* o = out + (size_t)(n0 + i) * 128;
            o[p0] = hsum2(p[i][0]) + bz0;
            o[p1] = hsum2(p[i][1]) + bz1;
            o[p2] = hsum2(p[i][2]) + bz2;
            o[p3] = hsum2(p[i][3]) + bz3;
        }
    }
}

// ---------------- layer-0 node pre (launch idx 2) ----------------
__global__ void __launch_bounds__(512, 1) k_pre0(const float* __restrict__ w1, const float* __restrict__ b1g) {
    extern __shared__ float sm[];
    float* sPreT = sm;
    float* sScr  = sm + 17408;
    int tid = threadIdx.x;
    for (int i = tid; i < 16384; i += 512) {
        int k = i >> 7, c = i & 127;
        int row = (k < 64) ? c : (128 + c);
        sPreT[row * 68 + (k & 63)] = w1[i];
    }
    __syncthreads();
    int lane = tid & 31, warp = tid >> 5;
    float* scrN = sScr + warp * 256;
    const int p0 = permp(lane), p1 = permp(lane + 32), p2 = permp(lane + 64), p3 = permp(lane + 96);
    const int stride = gridDim.x * 16;
    for (int g = blockIdx.x * 16 + warp; g < NN / 4; g += stride) {
        int n0 = g * 4;
        const float4* hsrc = (const float4*)(g_h + (size_t)n0 * 64);
        ((float4*)scrN)[lane]      = hsrc[lane];
        ((float4*)scrN)[lane + 32] = hsrc[lane + 32];
        __syncwarp();
        pre_group(sPreT, scrN, b1g, n0, lane, p0, p1, p2, p3);
        __syncwarp();
    }
}

// ---------------- smem layout for k_edge_mma ----------------
#define FRAG_U4   6144                  // 192 frags * 32 lanes
#define SM_BIAS2  (FRAG_U4 * 16)        // 98304 B : b2[64]
#define SM_Q1     (SM_BIAS2 + 256)
#define SM_Q2     (SM_Q1 + 256)
#define EDGE_SMEM (SM_Q2 + 256)         // 99072 B

#define FR1 0
#define FR2 (64 * 32)
#define FR3 (128 * 32)
#define FR4 (160 * 32)

// ---------------- mma.sync edge kernel: M=16/warp, 384 thr, permuted-coalesced gathers ----------------
__global__ void __launch_bounds__(384, 1) k_edge_mma(
    int layer, int store_e,
    const int* __restrict__ src, const int* __restrict__ dst,
    const float* __restrict__ b2,
    const float* __restrict__ pb1, const float* __restrict__ pb2)
{
    extern __shared__ char smem[];
    uint4* sm4 = (uint4*)smem;
    const int tid = threadIdx.x;

    {
        const uint4* srcf = g_frags + (size_t)layer * FRAG_U4;
        for (int i = tid; i < FRAG_U4; i += 384) sm4[i] = srcf[i];
        float* sB2 = (float*)(smem + SM_BIAS2);
        float* sQ1 = (float*)(smem + SM_Q1);
        float* sQ2 = (float*)(smem + SM_Q2);
        if (tid < 64) { sB2[tid] = b2[tid]; sQ1[tid] = pb1[tid]; sQ2[tid] = pb2[tid]; }
    }
    __syncthreads();

    const float* sB2f = (const float*)(smem + SM_BIAS2);
    const float* sQ1f = (const float*)(smem + SM_Q1);
    const float* sQ2f = (const float*)(smem + SM_Q2);

    const int wid = tid >> 5, lane = tid & 31;
    const int gr = lane >> 2;
    const int q  = lane & 3;
    const int t2 = 2 * q;

    const int NTILES = NE / 16;          // 50000
    const int wstride = gridDim.x * 12;

    int tile = blockIdx.x * 12 + wid;
    int pis0 = 0, pis8 = 0, pid0 = 0, pid8 = 0;
    if (tile < NTILES) {
        pis0 = __ldg(src + tile * 16 + gr);  pis8 = __ldg(src + tile * 16 + gr + 8);
        pid0 = __ldg(dst + tile * 16 + gr);  pid8 = __ldg(dst + tile * 16 + gr + 8);
    }

    for (; tile < NTILES; tile += wstride) {
        const int base = tile * 16;
        const int r0 = base + gr, r1 = base + gr + 8;
        const int is0 = pis0, is8 = pis8, id0 = pid0, id8 = pid8;
        {
            int tn = tile + wstride;
            if (tn < NTILES) {
                pis0 = __ldg(src + tn * 16 + gr); pis8 = __ldg(src + tn * 16 + gr + 8);
                pid0 = __ldg(dst + tn * 16 + gr); pid8 = __ldg(dst + tn * 16 + gr + 8);
            }
        }

        // ============ stage 1: c1 init = hs[src] + hd[dst] (permuted, coalesced float4) ============
        float c1[16][4];
        {
            const float4* hs0 = (const float4*)(g_hs + (size_t)is0 * 128);
            const float4* hd0 = (const float4*)(g_hd + (size_t)id0 * 128);
            const float4* hs8 = (const float4*)(g_hs + (size_t)is8 * 128);
            const float4* hd8 = (const float4*)(g_hd + (size_t)id8 * 128);
#pragma unroll
            for (int j = 0; j < 8; j++) {
                float4 a = __ldg(hs0 + 4 * j + q);
                float4 b = __ldg(hd0 + 4 * j + q);
                float4 c = __ldg(hs8 + 4 * j + q);
                float4 d = __ldg(hd8 + 4 * j + q);
                c1[2 * j][0]     = a.x + b.x; c1[2 * j][1]     = a.y + b.y;
                c1[2 * j + 1][0] = a.z + b.z; c1[2 * j + 1][1] = a.w + b.w;
                c1[2 * j][2]     = c.x + d.x; c1[2 * j][3]     = c.y + d.y;
                c1[2 * j + 1][2] = c.z + d.z; c1[2 * j + 1][3] = c.w + d.w;
            }
        }
        // ============ stage 1 cont.: c1 += e @ W1c ============
        {
            const uint2* pe0 = g_ebf + (size_t)r0 * 32;
            const uint2* pe1 = g_ebf + (size_t)r1 * 32;
            uint2 h0b[2], h1b[2], l0b[2], l1b[2];
            h0b[0] = __ldg(pe0 + q);      h1b[0] = __ldg(pe1 + q);
            l0b[0] = __ldg(pe0 + 16 + q); l1b[0] = __ldg(pe1 + 16 + q);
#pragma unroll
            for (int kt = 0; kt < 4; kt++) {
                const int cb = kt & 1, nb = cb ^ 1;
                if (kt < 3) {
                    h0b[nb] = __ldg(pe0 + 4 * (kt + 1) + q);      h1b[nb] = __ldg(pe1 + 4 * (kt + 1) + q);
                    l0b[nb] = __ldg(pe0 + 16 + 4 * (kt + 1) + q); l1b[nb] = __ldg(pe1 + 16 + 4 * (kt + 1) + q);
                }
                const uint4* fp = sm4 + FR1 + (size_t)kt * 512 + lane;
#pragma unroll
                for (int nt = 0; nt < 16; nt++) {
                    uint4 f = fp[nt * 32];
                    mma_bf16(c1[nt], h0b[cb].x, h1b[cb].x, h0b[cb].y, h1b[cb].y, f.x, f.y);
                    mma_bf16(c1[nt], l0b[cb].x, l1b[cb].x, l0b[cb].y, l1b[cb].y, f.x, f.y);
                    mma_bf16(c1[nt], h0b[cb].x, h1b[cb].x, h0b[cb].y, h1b[cb].y, f.z, f.w);
                }
            }
        }

        // ============ epi1+stage2 interleaved per kt: C2 = ssp(C1) @ W2 ============
        float c2[8][4];
#pragma unroll
        for (int nt = 0; nt < 8; nt++) { c2[nt][0] = c2[nt][1] = c2[nt][2] = c2[nt][3] = 0.f; }
#pragma unroll 1
        for (int kt = 0; kt < 8; kt++) {
            uint32_t a2h[4], a2l[4];
#pragma unroll
            for (int half = 0; half < 2; half++) {
                int nt = 2 * kt + half;
                float v0 = ssp_f(c1[nt][0]), v1 = ssp_f(c1[nt][1]);
                float v2 = ssp_f(c1[nt][2]), v3 = ssp_f(c1[nt][3]);
                bfsplit2(v0, v1, a2h[2 * half],     a2l[2 * half]);
                bfsplit2(v2, v3, a2h[2 * half + 1], a2l[2 * half + 1]);
            }
            const uint4* fp = sm4 + FR2 + (size_t)kt * 8 * 32 + lane;
#pragma unroll
            for (int nt = 0; nt < 8; nt++) {
                uint4 f = fp[nt * 32];
                mma_bf16(c2[nt], a2h[0], a2h[1], a2h[2], a2h[3], f.x, f.y);
                mma_bf16(c2[nt], a2l[0], a2l[1], a2l[2], a2l[3], f.x, f.y);
                mma_bf16(c2[nt], a2h[0], a2h[1], a2h[2], a2h[3], f.z, f.w);
            }
        }

        // ============ epi2+stage3 interleaved: C3 = (C2+b2) @ P1 ; e' -> g_ebf ============
        float c3[8][4];
#pragma unroll
        for (int nt = 0; nt < 8; nt++) { c3[nt][0] = c3[nt][1] = c3[nt][2] = c3[nt][3] = 0.f; }
#pragma unroll 1
        for (int kt = 0; kt < 4; kt++) {
            uint32_t a3h[4], a3l[4];
#pragma unroll
            for (int half = 0; half < 2; half++) {
                int nt = 2 * kt + half;
                float2 bb = *(const float2*)(sB2f + nt * 8 + t2);
                float x0 = c2[nt][0] + bb.x, x1 = c2[nt][1] + bb.y;
                float x2 = c2[nt][2] + bb.x, x3 = c2[nt][3] + bb.y;
                bfsplit2(x0, x1, a3h[2 * half],     a3l[2 * half]);
                bfsplit2(x2, x3, a3h[2 * half + 1], a3l[2 * half + 1]);
            }
            if (store_e) {
                uint2* pe0 = g_ebf + (size_t)r0 * 32;
                uint2* pe1 = g_ebf + (size_t)r1 * 32;
                pe0[4 * kt + q]      = make_uint2(a3h[0], a3h[2]);
                pe1[4 * kt + q]      = make_uint2(a3h[1], a3h[3]);
                pe0[16 + 4 * kt + q] = make_uint2(a3l[0], a3l[2]);
                pe1[16 + 4 * kt + q] = make_uint2(a3l[1], a3l[3]);
            }
            const uint4* fp = sm4 + FR3 + (size_t)kt * 8 * 32 + lane;
#pragma unroll
            for (int nt = 0; nt < 8; nt++) {
                uint4 f = fp[nt * 32];
                mma_bf16(c3[nt], a3h[0], a3h[1], a3h[2], a3h[3], f.x, f.y);
                mma_bf16(c3[nt], a3l[0], a3l[1], a3l[2], a3l[3], f.x, f.y);
                mma_bf16(c3[nt], a3h[0], a3h[1], a3h[2], a3h[3], f.z, f.w);
            }
        }

        // ============ epi3+stage4 interleaved: C4 = ssp(C3+q1) @ P2 ============
        float c4[8][4];
#pragma unroll
        for (int nt = 0; nt < 8; nt++) { c4[nt][0] = c4[nt][1] = c4[nt][2] = c4[nt][3] = 0.f; }
#pragma unroll 1
        for (int kt = 0; kt < 4; kt++) {
            uint32_t a4h[4], a4l[4];
#pragma unroll
            for (int half = 0; half < 2; half++) {
                int nt = 2 * kt + half;
                float2 bb = *(const float2*)(sQ1f + nt * 8 + t2);
                float v0 = ssp_f(c3[nt][0] + bb.x), v1 = ssp_f(c3[nt][1] + bb.y);
                float v2 = ssp_f(c3[nt][2] + bb.x), v3 = ssp_f(c3[nt][3] + bb.y);
                bfsplit2(v0, v1, a4h[2 * half],     a4l[2 * half]);
                bfsplit2(v2, v3, a4h[2 * half + 1], a4l[2 * half + 1]);
            }
            const uint4* fp = sm4 + FR4 + (size_t)kt * 8 * 32 + lane;
#pragma unroll
            for (int nt = 0; nt < 8; nt++) {
                uint4 f = fp[nt * 32];
                mma_bf16(c4[nt], a4h[0], a4h[1], a4h[2], a4h[3], f.x, f.y);
                mma_bf16(c4[nt], a4l[0], a4l[1], a4l[2], a4l[3], f.x, f.y);
                mma_bf16(c4[nt], a4h[0], a4h[1], a4h[2], a4h[3], f.z, f.w);
            }
        }

        // ============ epi4: he = C4 + q2; scatter-add to g_agg[dst] ============
        {
            float* da = g_agg + (size_t)id0 * 64;
            float* db = g_agg + (size_t)id8 * 64;
#pragma unroll
            for (int nt = 0; nt < 8; nt++) {
                float2 bb = *(const float2*)(sQ2f + nt * 8 + t2);
                float x0 = c4[nt][0] + bb.x, x1 = c4[nt][1] + bb.y;
                float x2 = c4[nt][2] + bb.x, x3 = c4[nt][3] + bb.y;
                asm volatile("red.global.add.v2.f32 [%0], {%1, %2};"
                             :: "l"(da + nt * 8 + t2), "f"(x0), "f"(x1) : "memory");
                asm volatile("red.global.add.v2.f32 [%0], {%1, %2};"
                             :: "l"(db + nt * 8 + t2), "f"(x2), "f"(x3) : "memory");
            }
        }
    }
}

// ---------------- node update: h += ssp(agg@A+ba)@B + bb; agg=0; fused next-layer pre ----------------
#define UPD_SMEM_FLOATS 30336
__global__ void __launch_bounds__(512, 1) k_update(
    const float* __restrict__ wa, const float* __restrict__ ba,
    const float* __restrict__ wb, const float* __restrict__ bb_,
    const float* __restrict__ w1next, const float* __restrict__ b1next, int do_pre)
{
    extern __shared__ float sm[];
    float* sPreT = sm;
    float* sAT   = sm + 17408;
    float* sBT   = sm + 21760;
    float* sBa   = sm + 26112;
    float* sBb   = sm + 26176;
    float* sScr  = sm + 26240;
    int tid = threadIdx.x;
    for (int i = tid; i < 4096; i += 512) {
        int k = i >> 6, c = i & 63;
        sAT[c * 68 + k] = wa[i];
        sBT[c * 68 + k] = wb[i];
    }
    if (do_pre) {
        for (int i = tid; i < 16384; i += 512) {
            int k = i >> 7, c = i & 127;
            int row = (k < 64) ? c : (128 + c);
            sPreT[row * 68 + (k & 63)] = w1next[i];
        }
    }
    if (tid < 64) { sBa[tid] = ba[tid]; sBb[tid] = bb_[tid]; }
    __syncthreads();

    int lane = tid & 31, warp = tid >> 5;
    float* scrN = sScr + warp * 256;
    const float bav0 = sBa[lane], bav1 = sBa[lane + 32];
    const float bbv0 = sBb[lane], bbv1 = sBb[lane + 32];
    const float* a0p = sAT + lane * 68;
    const float* a1p = sAT + (lane + 32) * 68;
    const float* b0p = sBT + lane * 68;
    const float* b1p = sBT + (lane + 32) * 68;
    const int p0 = permp(lane), p1 = permp(lane + 32), p2 = permp(lane + 64), p3 = permp(lane + 96);
    const int stride = gridDim.x * 16;

    for (int g = blockIdx.x * 16 + warp; g < NN / 4; g += stride) {
        int n0 = g * 4;
        float4* av = (float4*)(g_agg + (size_t)n0 * 64);
        float4 z = make_float4(0.f, 0.f, 0.f, 0.f);
        float4 t0 = av[lane], t1v = av[lane + 32];
        ((float4*)scrN)[lane] = t0; ((float4*)scrN)[lane + 32] = t1v;
        av[lane] = z; av[lane + 32] = z;
        __syncwarp();
        u64 aa[4][2];
#pragma unroll
        for (int i = 0; i < 4; i++) { aa[i][0] = pack2(bav0, 0.f); aa[i][1] = pack2(bav1, 0.f); }
#pragma unroll 4
        for (int k = 0; k < 64; k += 4) {
            ulonglong2 w0 = *(const ulonglong2*)(a0p + k);
            ulonglong2 w1 = *(const ulonglong2*)(a1p + k);
#pragma unroll
            for (int i = 0; i < 4; i++) {
                ulonglong2 tt = *(const ulonglong2*)(scrN + i * 64 + k);
                fma2(aa[i][0], tt.x, w0.x); fma2(aa[i][0], tt.y, w0.y);
                fma2(aa[i][1], tt.x, w1.x); fma2(aa[i][1], tt.y, w1.y);
            }
        }
        __syncwarp();
#pragma unroll
        for (int i = 0; i < 4; i++) {
            scrN[i * 64 + lane]      = ssp_f(hsum2(aa[i][0]));
            scrN[i * 64 + lane + 32] = ssp_f(hsum2(aa[i][1]));
        }
        __syncwarp();
        u64 oo[4][2];
#pragma unroll
        for (int i = 0; i < 4; i++) { oo[i][0] = pack2(bbv0, 0.f); oo[i][1] = pack2(bbv1, 0.f); }
#pragma unroll 4
        for (int k = 0; k < 64; k += 4) {
            ulonglong2 w0 = *(const ulonglong2*)(b0p + k);
            ulonglong2 w1 = *(const ulonglong2*)(b1p + k);
#pragma unroll
            for (int i = 0; i < 4; i++) {
                ulonglong2 tt = *(const ulonglong2*)(scrN + i * 64 + k);
                fma2(oo[i][0], tt.x, w0.x); fma2(oo[i][0], tt.y, w0.y);
                fma2(oo[i][1], tt.x, w1.x); fma2(oo[i][1], tt.y, w1.y);
            }
        }
        __syncwarp();
#pragma unroll
        for (int i = 0; i < 4; i++) {
            float* hp = g_h + (size_t)(n0 + i) * 64;
            float h0 = hp[lane]      + hsum2(oo[i][0]);
            float h1 = hp[lane + 32] + hsum2(oo[i][1]);
            hp[lane] = h0; hp[lane + 32] = h1;
            scrN[i * 64 + lane] = h0; scrN[i * 64 + lane + 32] = h1;
        }
        __syncwarp();
        if (do_pre) { pre_group(sPreT, scrN, b1next, n0, lane, p0, p1, p2, p3); }
        __syncwarp();
    }
}

// ---------------- readout + per-graph mean ----------------
__global__ void __launch_bounds__(256) k_readout(
    const int* __restrict__ gid,
    const float* __restrict__ d1w, const float* __restrict__ d1b,
    const float* __restrict__ d2w, const float* __restrict__ d2b)
{
    __shared__ float sW[2048], sB1r[32], sW2r[32];
    __shared__ float sB2r;
    int tid = threadIdx.x;
    for (int i = tid; i < 2048; i += 256) sW[i] = d1w[i];
    if (tid < 32) { sB1r[tid] = d1b[tid]; sW2r[tid] = d2w[tid]; }
    if (tid == 0) sB2r = d2b[0];
    __syncthreads();
    int lane = tid & 31, warp = tid >> 5;
    int nw = gridDim.x * 8;
    for (int n = blockIdx.x * 8 + warp; n < NN; n += nw) {
        float2 hv = *(const float2*)(g_h + (size_t)n * 64 + 2 * lane);
        float a = sB1r[lane];
#pragma unroll 8
        for (int k = 0; k < 64; k++) {
            float ek = __shfl_sync(0xffffffffu, (k & 1) ? hv.y : hv.x, k >> 1);
            a = fmaf(ek, sW[k * 32 + lane], a);
        }
        float p = ssp_f(a) * sW2r[lane];
#pragma unroll
        for (int off = 16; off; off >>= 1) p += __shfl_xor_sync(0xffffffffu, p, off);
        if (lane == 0) {
            int g = gid[n];
            atomicAdd(&g_sums[g], p + sB2r);
            atomicAdd(&g_cnt[g], 1.0f);
        }
    }
}

__global__ void k_final(float* __restrict__ out) {
    int t = threadIdx.x;
    if (t < NG) out[t] = g_sums[t] / fmaxf(g_cnt[t], 1.0f);
}

// ---------------- launch ----------------
extern "C" void kernel_launch(void* const* d_in, const int* in_sizes, int n_in,
                              void* d_out, int out_size) {
    const int*   az     = (const int*)d_in[0];
    const float* dist   = (const float*)d_in[1];
    const int*   src    = (const int*)d_in[2];
    const int*   dst    = (const int*)d_in[3];
    const int*   gid    = (const int*)d_in[4];
    const float* emb    = (const float*)d_in[5];
    const float* eu_w1  = (const float*)d_in[6];
    const float* eu_b1  = (const float*)d_in[7];
    const float* eu_w2  = (const float*)d_in[8];
    const float* eu_b2  = (const float*)d_in[9];
    const float* pe1_w  = (const float*)d_in[10];
    const float* pe1_b  = (const float*)d_in[11];
    const float* pe2_w  = (const float*)d_in[12];
    const float* pe2_b  = (const float*)d_in[13];
    const float* pn2a_w = (const float*)d_in[14];
    const float* pn2a_b = (const float*)d_in[15];
    const float* pn2b_w = (const float*)d_in[16];
    const float* pn2b_b = (const float*)d_in[17];
    const float* d1w    = (const float*)d_in[18];
    const float* d1b    = (const float*)d_in[19];
    const float* d2w    = (const float*)d_in[20];
    const float* d2b    = (const float*)d_in[21];

    cudaFuncSetAttribute(k_edge_mma, cudaFuncAttributeMaxDynamicSharedMemorySize, EDGE_SMEM);
    cudaFuncSetAttribute(k_update,   cudaFuncAttributeMaxDynamicSharedMemorySize, UPD_SMEM_FLOATS * 4);
    cudaFuncSetAttribute(k_pre0,     cudaFuncAttributeMaxDynamicSharedMemorySize, 21504 * 4);

    k_prep_zero<<<(3 * 6144 + 255) / 256, 256>>>(eu_w1, eu_w2, pe1_w, pe2_w);      // idx 0
    k_init_all<<<((NN + NE) * 16 + 255) / 256, 256>>>(az, emb, dist);              // idx 1
    k_pre0<<<148, 512, 21504 * 4>>>(eu_w1, eu_b1);                                 // idx 2

    for (int l = 0; l < 3; l++) {
        k_edge_mma<<<148, 384, EDGE_SMEM>>>(                                        // idx 3 (l=0)
            l, (l < 2) ? 1 : 0, src, dst,
            eu_b2 + l * 64, pe1_b + l * 64, pe2_b + l * 64);
        k_update<<<148, 512, UPD_SMEM_FLOATS * 4>>>(
            pn2a_w + (size_t)l * 4096, pn2a_b + l * 64,
            pn2b_w + (size_t)l * 4096, pn2b_b + l * 64,
            eu_w1 + (size_t)(l + 1) * 24576, eu_b1 + (size_t)(l + 1) * 128,
            (l < 2) ? 1 : 0);
    }
    k_readout<<<296, 256>>>(gid, d1w, d1b, d2w, d2b);
    k_final<<<1, 256>>>((float*)d_out);
}

// round 16
// speedup vs baseline: 1.1393x; 1.0123x over previous
#include <cuda_runtime.h>
#include <cuda_bf16.h>
#include <math.h>
#include <stdint.h>

#define NN 50000
#define NE 800000
#define NG 256
#define LN2F 0.69314718055994531f

// ---------------- scratch (device globals) ----------------
__device__ float g_h  [NN * 64];
// hs/hd rows stored PERMUTED: position p = 16*(nt>>1) + 4*(cc>>1) + 2*(nt&1) + (cc&1)
__device__ float g_hs [NN * 128];   // perm(h @ W1a + b1)  (fp32)
__device__ float g_hd [NN * 128];   // perm(h @ W1b)       (fp32)
__device__ float g_agg[NN * 64];
__device__ float g_sums[NG];
__device__ float g_cnt [NG];
// split-planar bf16 edge activations (A-fragment slot layout; 16 hi + 16 lo u64 slots/row)
__device__ uint2 g_ebf[(size_t)NE * 32];
// pre-packed B fragments: 3 layers x 192 frags x 32 lanes (uint4 = {bh01,bh23,bl01,bl23})
__device__ uint4 g_frags[3 * 6144];

typedef unsigned long long u64;

__device__ __forceinline__ u64 pack2(float lo, float hi) {
    u64 r; asm("mov.b64 %0, {%1, %2};" : "=l"(r) : "f"(lo), "f"(hi)); return r;
}
__device__ __forceinline__ void fma2(u64 &d, u64 a, u64 b) {
    asm("fma.rn.f32x2 %0, %1, %2, %0;" : "+l"(d) : "l"(a), "l"(b));
}
__device__ __forceinline__ float hsum2(u64 v) {
    float lo, hi; asm("mov.b64 {%0, %1}, %2;" : "=f"(lo), "=f"(hi) : "l"(v));
    return lo + hi;
}
__device__ __forceinline__ float ssp_f(float x) {
    return fmaxf(x, 0.0f) + __logf(1.0f + __expf(-fabsf(x))) - LN2F;
}
__device__ __forceinline__ void bfsplit2(float a, float b, uint32_t &hi, uint32_t &lo) {
    __nv_bfloat16 ha = __float2bfloat16_rn(a), hb = __float2bfloat16_rn(b);
    hi = (uint32_t)__bfloat16_as_ushort(ha) | ((uint32_t)__bfloat16_as_ushort(hb) << 16);
    __nv_bfloat16 la = __float2bfloat16_rn(a - __bfloat162float(ha));
    __nv_bfloat16 lb = __float2bfloat16_rn(b - __bfloat162float(hb));
    lo = (uint32_t)__bfloat16_as_ushort(la) | ((uint32_t)__bfloat16_as_ushort(lb) << 16);
}
// permuted position for logical column c (0..127)
__device__ __forceinline__ int permp(int c) {
    int nt = c >> 3, cc = c & 7;
    return 16 * (nt >> 1) + 4 * (cc >> 1) + 2 * (nt & 1) + (cc & 1);
}
// RBF A-fragment slots for distance d at column base k1: hi/lo packed pairs
__device__ __forceinline__ void rbf_frag(float d, int k1, uint32_t &h, uint32_t &l,
                                         uint32_t &h2, uint32_t &l2) {
    const float gap = 63.0f / 5.0f, step = 5.0f / 63.0f;
    float df0 = d - step * (float)(k1);
    float df1 = d - step * (float)(k1 + 1);
    float df2 = d - step * (float)(k1 + 8);
    float df3 = d - step * (float)(k1 + 9);
    float v0 = __expf(-df0 * df0 * gap);
    float v1 = __expf(-df1 * df1 * gap);
    float v2 = __expf(-df2 * df2 * gap);
    float v3 = __expf(-df3 * df3 * gap);
    bfsplit2(v0, v1, h, l);
    bfsplit2(v2, v3, h2, l2);
}

__device__ __forceinline__ void mma_bf16(float* c,
    uint32_t a0, uint32_t a1, uint32_t a2, uint32_t a3, uint32_t b0, uint32_t b1) {
    asm("mma.sync.aligned.m16n8k16.row.col.f32.bf16.bf16.f32 "
        "{%0,%1,%2,%3}, {%4,%5,%6,%7}, {%8,%9}, {%0,%1,%2,%3};"
        : "+f"(c[0]), "+f"(c[1]), "+f"(c[2]), "+f"(c[3])
        : "r"(a0), "r"(a1), "r"(a2), "r"(a3), "r"(b0), "r"(b1));
}

// ---------------- fragment prep + pool zero (launch idx 0) ----------------
__global__ void k_prep_zero(const float* __restrict__ eu_w1, const float* __restrict__ eu_w2,
                            const float* __restrict__ pe1_w, const float* __restrict__ pe2_w) {
    int s = blockIdx.x * blockDim.x + threadIdx.x;
    if (s < NG) { g_sums[s] = 0.f; g_cnt[s] = 0.f; }
    if (s >= 3 * 6144) return;
    int l = s / 6144, r = s % 6144;
    int f = r >> 5, lane = r & 31;
    const float* W; int NT, N, fl;
    if (f < 64)       { W = eu_w1 + (size_t)l * 24576 + 16384; fl = f;       NT = 16; N = 128; }
    else if (f < 128) { W = eu_w2 + (size_t)l * 8192;          fl = f - 64;  NT = 8;  N = 64; }
    else if (f < 160) { W = pe1_w + (size_t)l * 4096;          fl = f - 128; NT = 8;  N = 64; }
    else              { W = pe2_w + (size_t)l * 4096;          fl = f - 160; NT = 8;  N = 64; }
    int nt = fl % NT, kst = fl / NT;
    int n  = nt * 8 + (lane >> 2);
    int k0 = kst * 16 + 2 * (lane & 3);
    float w0 = W[(size_t)k0 * N + n];
    float w1 = W[(size_t)(k0 + 1) * N + n];
    float w2 = W[(size_t)(k0 + 8) * N + n];
    float w3 = W[(size_t)(k0 + 9) * N + n];
    uint32_t h01, l01, h23, l23;
    bfsplit2(w0, w1, h01, l01);
    bfsplit2(w2, w3, h23, l23);
    g_frags[s] = make_uint4(h01, h23, l01, l23);
}

// ---------------- node init: g_h + agg zero (launch idx 1) ----------------
__global__ void k_init_nodes(const int* __restrict__ az, const float* __restrict__ emb) {
    int t = blockIdx.x * blockDim.x + threadIdx.x;
    if (t >= NN * 16) return;
    int n = t >> 4, s = t & 15;
    int z = __ldg(az + n);
    float4 v = __ldg((const float4*)(emb + (size_t)z * 64) + s);
    ((float4*)(g_h + (size_t)n * 64))[s] = v;
    ((float4*)(g_agg + (size_t)n * 64))[s] = make_float4(0.f, 0.f, 0.f, 0.f);
}

// ---------------- node-pre device function (fp32, fma2); writes PERMUTED hs/hd ----------------
__device__ __forceinline__ void pre_group(const float* __restrict__ sPreT,
                                          const float* __restrict__ scrN,
                                          const float* __restrict__ b1g,
                                          int n0, int lane,
                                          int p0, int p1, int p2, int p3) {
#pragma unroll
    for (int half = 0; half < 2; half++) {
        u64 p[4][4];
#pragma unroll
        for (int i = 0; i < 4; i++)
#pragma unroll
            for (int j = 0; j < 4; j++) p[i][j] = 0ULL;
        const float* w0 = sPreT + (half * 128 + lane     ) * 68;
        const float* w1 = sPreT + (half * 128 + lane + 32) * 68;
        const float* w2 = sPreT + (half * 128 + lane + 64) * 68;
        const float* w3 = sPreT + (half * 128 + lane + 96) * 68;
#pragma unroll 4
        for (int k = 0; k < 64; k += 4) {
            ulonglong2 a = *(const ulonglong2*)(w0 + k);
            ulonglong2 b = *(const ulonglong2*)(w1 + k);
            ulonglong2 c = *(const ulonglong2*)(w2 + k);
            ulonglong2 d = *(const ulonglong2*)(w3 + k);
#pragma unroll
            for (int i = 0; i < 4; i++) {
                ulonglong2 t = *(const ulonglong2*)(scrN + i * 64 + k);
                fma2(p[i][0], t.x, a.x); fma2(p[i][0], t.y, a.y);
                fma2(p[i][1], t.x, b.x); fma2(p[i][1], t.y, b.y);
                fma2(p[i][2], t.x, c.x); fma2(p[i][2], t.y, c.y);
                fma2(p[i][3], t.x, d.x); fma2(p[i][3], t.y, d.y);
            }
        }
        float bz0 = 0.f, bz1 = 0.f, bz2 = 0.f, bz3 = 0.f;
        if (half == 0) {
            bz0 = __ldg(b1g + lane);      bz1 = __ldg(b1g + lane + 32);
            bz2 = __ldg(b1g + lane + 64); bz3 = __ldg(b1g + lane + 96);
        }
        float* out = (half == 0) ? g_hs : g_hd;
#pragma unroll
        for (int i = 0; i < 4; i++) {
            float* o = out + (size_t)(n0 + i) * 128;
            o[p0] = hsum2(p[i][0]) + bz0;
            o[p1] = hsum2(p[i][1]) + bz1;
            o[p2] = hsum2(p[i][2]) + bz2;
            o[p3] = hsum2(p[i][3]) + bz3;
        }
    }
}

// ---------------- layer-0 node pre (launch idx 2) ----------------
__global__ void __launch_bounds__(512, 1) k_pre0(const float* __restrict__ w1, const float* __restrict__ b1g) {
    extern __shared__ float sm[];
    float* sPreT = sm;
    float* sScr  = sm + 17408;
    int tid = threadIdx.x;
    for (int i = tid; i < 16384; i += 512) {
        int k = i >> 7, c = i & 127;
        int row = (k < 64) ? c : (128 + c);
        sPreT[row * 68 + (k & 63)] = w1[i];
    }
    __syncthreads();
    int lane = tid & 31, warp = tid >> 5;
    float* scrN = sScr + warp * 256;
    const int p0 = permp(lane), p1 = permp(lane + 32), p2 = permp(lane + 64), p3 = permp(lane + 96);
    const int stride = gridDim.x * 16;
    for (int g = blockIdx.x * 16 + warp; g < NN / 4; g += stride) {
        int n0 = g * 4;
        const float4* hsrc = (const float4*)(g_h + (size_t)n0 * 64);
        ((float4*)scrN)[lane]      = hsrc[lane];
        ((float4*)scrN)[lane + 32] = hsrc[lane + 32];
        __syncwarp();
        pre_group(sPreT, scrN, b1g, n0, lane, p0, p1, p2, p3);
        __syncwarp();
    }
}

// ---------------- smem layout for k_edge_mma ----------------
#define FRAG_U4   6144                  // 192 frags * 32 lanes
#define SM_BIAS2  (FRAG_U4 * 16)        // 98304 B : b2[64]
#define SM_Q1     (SM_BIAS2 + 256)
#define SM_Q2     (SM_Q1 + 256)
#define EDGE_SMEM (SM_Q2 + 256)         // 99072 B

#define FR1 0
#define FR2 (64 * 32)
#define FR3 (128 * 32)
#define FR4 (160 * 32)

// ---------------- mma.sync edge kernel: M=16/warp, 384 thr; layer-0 RBF computed in-kernel ----------------
__global__ void __launch_bounds__(384, 1) k_edge_mma(
    int layer, int store_e,
    const int* __restrict__ src, const int* __restrict__ dst,
    const float* __restrict__ dist,
    const float* __restrict__ b2,
    const float* __restrict__ pb1, const float* __restrict__ pb2)
{
    extern __shared__ char smem[];
    uint4* sm4 = (uint4*)smem;
    const int tid = threadIdx.x;

    {
        const uint4* srcf = g_frags + (size_t)layer * FRAG_U4;
        for (int i = tid; i < FRAG_U4; i += 384) sm4[i] = srcf[i];
        float* sB2 = (float*)(smem + SM_BIAS2);
        float* sQ1 = (float*)(smem + SM_Q1);
        float* sQ2 = (float*)(smem + SM_Q2);
        if (tid < 64) { sB2[tid] = b2[tid]; sQ1[tid] = pb1[tid]; sQ2[tid] = pb2[tid]; }
    }
    __syncthreads();

    const float* sB2f = (const float*)(smem + SM_BIAS2);
    const float* sQ1f = (const float*)(smem + SM_Q1);
    const float* sQ2f = (const float*)(smem + SM_Q2);

    const int wid = tid >> 5, lane = tid & 31;
    const int gr = lane >> 2;
    const int q  = lane & 3;
    const int t2 = 2 * q;

    const int NTILES = NE / 16;          // 50000
    const int wstride = gridDim.x * 12;

    int tile = blockIdx.x * 12 + wid;
    int pis0 = 0, pis8 = 0, pid0 = 0, pid8 = 0;
    if (tile < NTILES) {
        pis0 = __ldg(src + tile * 16 + gr);  pis8 = __ldg(src + tile * 16 + gr + 8);
        pid0 = __ldg(dst + tile * 16 + gr);  pid8 = __ldg(dst + tile * 16 + gr + 8);
    }

    for (; tile < NTILES; tile += wstride) {
        const int base = tile * 16;
        const int r0 = base + gr, r1 = base + gr + 8;
        const int is0 = pis0, is8 = pis8, id0 = pid0, id8 = pid8;
        {
            int tn = tile + wstride;
            if (tn < NTILES) {
                pis0 = __ldg(src + tn * 16 + gr); pis8 = __ldg(src + tn * 16 + gr + 8);
                pid0 = __ldg(dst + tn * 16 + gr); pid8 = __ldg(dst + tn * 16 + gr + 8);
            }
        }

        // ============ stage 1: c1 init = hs[src] + hd[dst] (permuted, coalesced float4) ============
        float c1[16][4];
        {
            const float4* hs0 = (const float4*)(g_hs + (size_t)is0 * 128);
            const float4* hd0 = (const float4*)(g_hd + (size_t)id0 * 128);
            const float4* hs8 = (const float4*)(g_hs + (size_t)is8 * 128);
            const float4* hd8 = (const float4*)(g_hd + (size_t)id8 * 128);
#pragma unroll
            for (int j = 0; j < 8; j++) {
                float4 a = __ldg(hs0 + 4 * j + q);
                float4 b = __ldg(hd0 + 4 * j + q);
                float4 c = __ldg(hs8 + 4 * j + q);
                float4 d = __ldg(hd8 + 4 * j + q);
                c1[2 * j][0]     = a.x + b.x; c1[2 * j][1]     = a.y + b.y;
                c1[2 * j + 1][0] = a.z + b.z; c1[2 * j + 1][1] = a.w + b.w;
                c1[2 * j][2]     = c.x + d.x; c1[2 * j][3]     = c.y + d.y;
                c1[2 * j + 1][2] = c.z + d.z; c1[2 * j + 1][3] = c.w + d.w;
            }
        }
        // ============ stage 1 cont.: c1 += e @ W1c ============
        if (layer == 0) {
            // RBF computed in-register from dist (no g_ebf traffic)
            const float d0 = __ldg(dist + r0);
            const float d1 = __ldg(dist + r1);
#pragma unroll
            for (int kt = 0; kt < 4; kt++) {
                const int k1 = 16 * kt + t2;
                uint32_t h0x, l0x, h0y, l0y, h1x, l1x, h1y, l1y;
                rbf_frag(d0, k1, h0x, l0x, h0y, l0y);
                rbf_frag(d1, k1, h1x, l1x, h1y, l1y);
                const uint4* fp = sm4 + FR1 + (size_t)kt * 512 + lane;
#pragma unroll
                for (int nt = 0; nt < 16; nt++) {
                    uint4 f = fp[nt * 32];
                    mma_bf16(c1[nt], h0x, h1x, h0y, h1y, f.x, f.y);
                    mma_bf16(c1[nt], l0x, l1x, l0y, l1y, f.x, f.y);
                    mma_bf16(c1[nt], h0x, h1x, h0y, h1y, f.z, f.w);
                }
            }
        } else {
            const uint2* pe0 = g_ebf + (size_t)r0 * 32;
            const uint2* pe1 = g_ebf + (size_t)r1 * 32;
            uint2 h0b[2], h1b[2], l0b[2], l1b[2];
            h0b[0] = __ldg(pe0 + q);      h1b[0] = __ldg(pe1 + q);
            l0b[0] = __ldg(pe0 + 16 + q); l1b[0] = __ldg(pe1 + 16 + q);
#pragma unroll
            for (int kt = 0; kt < 4; kt++) {
                const int cb = kt & 1, nb = cb ^ 1;
                if (kt < 3) {
                    h0b[nb] = __ldg(pe0 + 4 * (kt + 1) + q);      h1b[nb] = __ldg(pe1 + 4 * (kt + 1) + q);
                    l0b[nb] = __ldg(pe0 + 16 + 4 * (kt + 1) + q); l1b[nb] = __ldg(pe1 + 16 + 4 * (kt + 1) + q);
                }
                const uint4* fp = sm4 + FR1 + (size_t)kt * 512 + lane;
#pragma unroll
                for (int nt = 0; nt < 16; nt++) {
                    uint4 f = fp[nt * 32];
                    mma_bf16(c1[nt], h0b[cb].x, h1b[cb].x, h0b[cb].y, h1b[cb].y, f.x, f.y);
                    mma_bf16(c1[nt], l0b[cb].x, l1b[cb].x, l0b[cb].y, l1b[cb].y, f.x, f.y);
                    mma_bf16(c1[nt], h0b[cb].x, h1b[cb].x, h0b[cb].y, h1b[cb].y, f.z, f.w);
                }
            }
        }

        // ============ epi1+stage2 interleaved per kt: C2 = ssp(C1) @ W2 ============
        float c2[8][4];
#pragma unroll
        for (int nt = 0; nt < 8; nt++) { c2[nt][0] = c2[nt][1] = c2[nt][2] = c2[nt][3] = 0.f; }
#pragma unroll 1
        for (int kt = 0; kt < 8; kt++) {
            uint32_t a2h[4], a2l[4];
#pragma unroll
            for (int half = 0; half < 2; half++) {
                int nt = 2 * kt + half;
                float v0 = ssp_f(c1[nt][0]), v1 = ssp_f(c1[nt][1]);
                float v2 = ssp_f(c1[nt][2]), v3 = ssp_f(c1[nt][3]);
                bfsplit2(v0, v1, a2h[2 * half],     a2l[2 * half]);
                bfsplit2(v2, v3, a2h[2 * half + 1], a2l[2 * half + 1]);
            }
            const uint4* fp = sm4 + FR2 + (size_t)kt * 8 * 32 + lane;
#pragma unroll
            for (int nt = 0; nt < 8; nt++) {
                uint4 f = fp[nt * 32];
                mma_bf16(c2[nt], a2h[0], a2h[1], a2h[2], a2h[3], f.x, f.y);
                mma_bf16(c2[nt], a2l[0], a2l[1], a2l[2], a2l[3], f.x, f.y);
                mma_bf16(c2[nt], a2h[0], a2h[1], a2h[2], a2h[3], f.z, f.w);
            }
        }

        // ============ epi2+stage3 interleaved: C3 = (C2+b2) @ P1 ; e' -> g_ebf ============
        float c3[8][4];
#pragma unroll
        for (int nt = 0; nt < 8; nt++) { c3[nt][0] = c3[nt][1] = c3[nt][2] = c3[nt][3] = 0.f; }
#pragma unroll 1
        for (int kt = 0; kt < 4; kt++) {
            uint32_t a3h[4], a3l[4];
#pragma unroll
            for (int half = 0; half < 2; half++) {
                int nt = 2 * kt + half;
                float2 bb = *(const float2*)(sB2f + nt * 8 + t2);
                float x0 = c2[nt][0] + bb.x, x1 = c2[nt][1] + bb.y;
                float x2 = c2[nt][2] + bb.x, x3 = c2[nt][3] + bb.y;
                bfsplit2(x0, x1, a3h[2 * half],     a3l[2 * half]);
                bfsplit2(x2, x3, a3h[2 * half + 1], a3l[2 * half + 1]);
            }
            if (store_e) {
                uint2* pe0 = g_ebf + (size_t)r0 * 32;
                uint2* pe1 = g_ebf + (size_t)r1 * 32;
                pe0[4 * kt + q]      = make_uint2(a3h[0], a3h[2]);
                pe1[4 * kt + q]      = make_uint2(a3h[1], a3h[3]);
                pe0[16 + 4 * kt + q] = make_uint2(a3l[0], a3l[2]);
                pe1[16 + 4 * kt + q] = make_uint2(a3l[1], a3l[3]);
            }
            const uint4* fp = sm4 + FR3 + (size_t)kt * 8 * 32 + lane;
#pragma unroll
            for (int nt = 0; nt < 8; nt++) {
                uint4 f = fp[nt * 32];
                mma_bf16(c3[nt], a3h[0], a3h[1], a3h[2], a3h[3], f.x, f.y);
                mma_bf16(c3[nt], a3l[0], a3l[1], a3l[2], a3l[3], f.x, f.y);
                mma_bf16(c3[nt], a3h[0], a3h[1], a3h[2], a3h[3], f.z, f.w);
            }
        }

        // ============ epi3+stage4 interleaved: C4 = ssp(C3+q1) @ P2 ============
        float c4[8][4];
#pragma unroll
        for (int nt = 0; nt < 8; nt++) { c4[nt][0] = c4[nt][1] = c4[nt][2] = c4[nt][3] = 0.f; }
#pragma unroll 1
        for (int kt = 0; kt < 4; kt++) {
            uint32_t a4h[4], a4l[4];
#pragma unroll
            for (int half = 0; half < 2; half++) {
                int nt = 2 * kt + half;
                float2 bb = *(const float2*)(sQ1f + nt * 8 + t2);
                float v0 = ssp_f(c3[nt][0] + bb.x), v1 = ssp_f(c3[nt][1] + bb.y);
                float v2 = ssp_f(c3[nt][2] + bb.x), v3 = ssp_f(c3[nt][3] + bb.y);
                bfsplit2(v0, v1, a4h[2 * half],     a4l[2 * half]);
                bfsplit2(v2, v3, a4h[2 * half + 1], a4l[2 * half + 1]);
            }
            const uint4* fp = sm4 + FR4 + (size_t)kt * 8 * 32 + lane;
#pragma unroll
            for (int nt = 0; nt < 8; nt++) {
                uint4 f = fp[nt * 32];
                mma_bf16(c4[nt], a4h[0], a4h[1], a4h[2], a4h[3], f.x, f.y);
                mma_bf16(c4[nt], a4l[0], a4l[1], a4l[2], a4l[3], f.x, f.y);
                mma_bf16(c4[nt], a4h[0], a4h[1], a4h[2], a4h[3], f.z, f.w);
            }
        }

        // ============ epi4: he = C4 + q2; scatter-add to g_agg[dst] ============
        {
            float* da = g_agg + (size_t)id0 * 64;
            float* db = g_agg + (size_t)id8 * 64;
#pragma unroll
            for (int nt = 0; nt < 8; nt++) {
                float2 bb = *(const float2*)(sQ2f + nt * 8 + t2);
                float x0 = c4[nt][0] + bb.x, x1 = c4[nt][1] + bb.y;
                float x2 = c4[nt][2] + bb.x, x3 = c4[nt][3] + bb.y;
                asm volatile("red.global.add.v2.f32 [%0], {%1, %2};"
                             :: "l"(da + nt * 8 + t2), "f"(x0), "f"(x1) : "memory");
                asm volatile("red.global.add.v2.f32 [%0], {%1, %2};"
                             :: "l"(db + nt * 8 + t2), "f"(x2), "f"(x3) : "memory");
            }
        }
    }
}

// ---------------- node update: h += ssp(agg@A+ba)@B + bb; agg=0; fused next-layer pre ----------------
#define UPD_SMEM_FLOATS 30336
__global__ void __launch_bounds__(512, 1) k_update(
    const float* __restrict__ wa, const float* __restrict__ ba,
    const float* __restrict__ wb, const float* __restrict__ bb_,
    const float* __restrict__ w1next, const float* __restrict__ b1next, int do_pre)
{
    extern __shared__ float sm[];
    float* sPreT = sm;
    float* sAT   = sm + 17408;
    float* sBT   = sm + 21760;
    float* sBa   = sm + 26112;
    float* sBb   = sm + 26176;
    float* sScr  = sm + 26240;
    int tid = threadIdx.x;
    for (int i = tid; i < 4096; i += 512) {
        int k = i >> 6, c = i & 63;
        sAT[c * 68 + k] = wa[i];
        sBT[c * 68 + k] = wb[i];
    }
    if (do_pre) {
        for (int i = tid; i < 16384; i += 512) {
            int k = i >> 7, c = i & 127;
            int row = (k < 64) ? c : (128 + c);
            sPreT[row * 68 + (k & 63)] = w1next[i];
        }
    }
    if (tid < 64) { sBa[tid] = ba[tid]; sBb[tid] = bb_[tid]; }
    __syncthreads();

    int lane = tid & 31, warp = tid >> 5;
    float* scrN = sScr + warp * 256;
    const float bav0 = sBa[lane], bav1 = sBa[lane + 32];
    const float bbv0 = sBb[lane], bbv1 = sBb[lane + 32];
    const float* a0p = sAT + lane * 68;
    const float* a1p = sAT + (lane + 32) * 68;
    const float* b0p = sBT + lane * 68;
    const float* b1p = sBT + (lane + 32) * 68;
    const int p0 = permp(lane), p1 = permp(lane + 32), p2 = permp(lane + 64), p3 = permp(lane + 96);
    const int stride = gridDim.x * 16;

    for (int g = blockIdx.x * 16 + warp; g < NN / 4; g += stride) {
        int n0 = g * 4;
        float4* av = (float4*)(g_agg + (size_t)n0 * 64);
        float4 z = make_float4(0.f, 0.f, 0.f, 0.f);
        float4 t0 = av[lane], t1v = av[lane + 32];
        ((float4*)scrN)[lane] = t0; ((float4*)scrN)[lane + 32] = t1v;
        av[lane] = z; av[lane + 32] = z;
        __syncwarp();
        u64 aa[4][2];
#pragma unroll
        for (int i = 0; i < 4; i++) { aa[i][0] = pack2(bav0, 0.f); aa[i][1] = pack2(bav1, 0.f); }
#pragma unroll 4
        for (int k = 0; k < 64; k += 4) {
            ulonglong2 w0 = *(const ulonglong2*)(a0p + k);
            ulonglong2 w1 = *(const ulonglong2*)(a1p + k);
#pragma unroll
            for (int i = 0; i < 4; i++) {
                ulonglong2 tt = *(const ulonglong2*)(scrN + i * 64 + k);
                fma2(aa[i][0], tt.x, w0.x); fma2(aa[i][0], tt.y, w0.y);
                fma2(aa[i][1], tt.x, w1.x); fma2(aa[i][1], tt.y, w1.y);
            }
        }
        __syncwarp();
#pragma unroll
        for (int i = 0; i < 4; i++) {
            scrN[i * 64 + lane]      = ssp_f(hsum2(aa[i][0]));
            scrN[i * 64 + lane + 32] = ssp_f(hsum2(aa[i][1]));
        }
        __syncwarp();
        u64 oo[4][2];
#pragma unroll
        for (int i = 0; i < 4; i++) { oo[i][0] = pack2(bbv0, 0.f); oo[i][1] = pack2(bbv1, 0.f); }
#pragma unroll 4
        for (int k = 0; k < 64; k += 4) {
            ulonglong2 w0 = *(const ulonglong2*)(b0p + k);
            ulonglong2 w1 = *(const ulonglong2*)(b1p + k);
#pragma unroll
            for (int i = 0; i < 4; i++) {
                ulonglong2 tt = *(const ulonglong2*)(scrN + i * 64 + k);
                fma2(oo[i][0], tt.x, w0.x); fma2(oo[i][0], tt.y, w0.y);
                fma2(oo[i][1], tt.x, w1.x); fma2(oo[i][1], tt.y, w1.y);
            }
        }
        __syncwarp();
#pragma unroll
        for (int i = 0; i < 4; i++) {
            float* hp = g_h + (size_t)(n0 + i) * 64;
            float h0 = hp[lane]      + hsum2(oo[i][0]);
            float h1 = hp[lane + 32] + hsum2(oo[i][1]);
            hp[lane] = h0; hp[lane + 32] = h1;
            scrN[i * 64 + lane] = h0; scrN[i * 64 + lane + 32] = h1;
        }
        __syncwarp();
        if (do_pre) { pre_group(sPreT, scrN, b1next, n0, lane, p0, p1, p2, p3); }
        __syncwarp();
    }
}

// ---------------- readout + per-graph mean ----------------
__global__ void __launch_bounds__(256) k_readout(
    const int* __restrict__ gid,
    const float* __restrict__ d1w, const float* __restrict__ d1b,
    const float* __restrict__ d2w, const float* __restrict__ d2b)
{
    __shared__ float sW[2048], sB1r[32], sW2r[32];
    __shared__ float sB2r;
    int tid = threadIdx.x;
    for (int i = tid; i < 2048; i += 256) sW[i] = d1w[i];
    if (tid < 32) { sB1r[tid] = d1b[tid]; sW2r[tid] = d2w[tid]; }
    if (tid == 0) sB2r = d2b[0];
    __syncthreads();
    int lane = tid & 31, warp = tid >> 5;
    int nw = gridDim.x * 8;
    for (int n = blockIdx.x * 8 + warp; n < NN; n += nw) {
        float2 hv = *(const float2*)(g_h + (size_t)n * 64 + 2 * lane);
        float a = sB1r[lane];
#pragma unroll 8
        for (int k = 0; k < 64; k++) {
            float ek = __shfl_sync(0xffffffffu, (k & 1) ? hv.y : hv.x, k >> 1);
            a = fmaf(ek, sW[k * 32 + lane], a);
        }
        float p = ssp_f(a) * sW2r[lane];
#pragma unroll
        for (int off = 16; off; off >>= 1) p += __shfl_xor_sync(0xffffffffu, p, off);
        if (lane == 0) {
            int g = gid[n];
            atomicAdd(&g_sums[g], p + sB2r);
            atomicAdd(&g_cnt[g], 1.0f);
        }
    }
}

__global__ void k_final(float* __restrict__ out) {
    int t = threadIdx.x;
    if (t < NG) out[t] = g_sums[t] / fmaxf(g_cnt[t], 1.0f);
}

// ---------------- launch ----------------
extern "C" void kernel_launch(void* const* d_in, const int* in_sizes, int n_in,
                              void* d_out, int out_size) {
    const int*   az     = (const int*)d_in[0];
    const float* dist   = (const float*)d_in[1];
    const int*   src    = (const int*)d_in[2];
    const int*   dst    = (const int*)d_in[3];
    const int*   gid    = (const int*)d_in[4];
    const float* emb    = (const float*)d_in[5];
    const float* eu_w1  = (const float*)d_in[6];
    const float* eu_b1  = (const float*)d_in[7];
    const float* eu_w2  = (const float*)d_in[8];
    const float* eu_b2  = (const float*)d_in[9];
    const float* pe1_w  = (const float*)d_in[10];
    const float* pe1_b  = (const float*)d_in[11];
    const float* pe2_w  = (const float*)d_in[12];
    const float* pe2_b  = (const float*)d_in[13];
    const float* pn2a_w = (const float*)d_in[14];
    const float* pn2a_b = (const float*)d_in[15];
    const float* pn2b_w = (const float*)d_in[16];
    const float* pn2b_b = (const float*)d_in[17];
    const float* d1w    = (const float*)d_in[18];
    const float* d1b    = (const float*)d_in[19];
    const float* d2w    = (const float*)d_in[20];
    const float* d2b    = (const float*)d_in[21];

    cudaFuncSetAttribute(k_edge_mma, cudaFuncAttributeMaxDynamicSharedMemorySize, EDGE_SMEM);
    cudaFuncSetAttribute(k_update,   cudaFuncAttributeMaxDynamicSharedMemorySize, UPD_SMEM_FLOATS * 4);
    cudaFuncSetAttribute(k_pre0,     cudaFuncAttributeMaxDynamicSharedMemorySize, 21504 * 4);

    k_prep_zero<<<(3 * 6144 + 255) / 256, 256>>>(eu_w1, eu_w2, pe1_w, pe2_w);      // idx 0
    k_init_nodes<<<(NN * 16 + 255) / 256, 256>>>(az, emb);                         // idx 1
    k_pre0<<<148, 512, 21504 * 4>>>(eu_w1, eu_b1);                                 // idx 2

    for (int l = 0; l < 3; l++) {
        k_edge_mma<<<148, 384, EDGE_SMEM>>>(                                        // idx 3 (l=0)
            l, (l < 2) ? 1 : 0, src, dst, dist,
            eu_b2 + l * 64, pe1_b + l * 64, pe2_b + l * 64);
        k_update<<<148, 512, UPD_SMEM_FLOATS * 4>>>(
            pn2a_w + (size_t)l * 4096, pn2a_b + l * 64,
            pn2b_w + (size_t)l * 4096, pn2b_b + l * 64,
            eu_w1 + (size_t)(l + 1) * 24576, eu_b1 + (size_t)(l + 1) * 128,
            (l < 2) ? 1 : 0);
    }
    k_readout<<<296, 256>>>(gid, d1w, d1b, d2w, d2b);
    k_final<<<1, 256>>>((float*)d_out);
}